// round 15
// baseline (speedup 1.0000x reference)
#include <cuda_runtime.h>
#include <cuda_bf16.h>
#include <stdint.h>
#include <math.h>

#define TT   4096
#define DD   1024
#define HH   512
#define EE   32
#define KTOP 4
#define CAP  2048
#define HS   1024

typedef __nv_bfloat16 bf16;

// ---------------- scratch (device globals; no allocations allowed) ----------
__device__ int   g_cnt[EE];
__device__ int   g_pid[EE * CAP];
__device__ float g_wt [EE * CAP];
__device__ float g_po [(size_t)TT * KTOP * DD];  // per-pair output

__device__ bf16 g_xhi [(size_t)TT * DD];
__device__ bf16 g_xlo [(size_t)TT * DD];
__device__ bf16 g_hhi [(size_t)EE * CAP * HH];   // routed hidden hi/lo
__device__ bf16 g_hlo [(size_t)EE * CAP * HH];
__device__ bf16 g_hshi[(size_t)TT * HS];         // shared hidden hi/lo
__device__ bf16 g_hslo[(size_t)TT * HS];

// pre-transposed + hi/lo split weights, K-major [n][k]
__device__ bf16 g_w1hi[(size_t)EE * HH * DD];
__device__ bf16 g_w1lo[(size_t)EE * HH * DD];
__device__ bf16 g_w3hi[(size_t)EE * HH * DD];
__device__ bf16 g_w3lo[(size_t)EE * HH * DD];
__device__ bf16 g_w2hi[(size_t)EE * DD * HH];
__device__ bf16 g_w2lo[(size_t)EE * DD * HH];
__device__ bf16 g_ws1hi[(size_t)HS * DD];
__device__ bf16 g_ws1lo[(size_t)HS * DD];
__device__ bf16 g_ws3hi[(size_t)HS * DD];
__device__ bf16 g_ws3lo[(size_t)HS * DD];
__device__ bf16 g_ws2hi[(size_t)DD * HS];
__device__ bf16 g_ws2lo[(size_t)DD * HS];

// ---------------- helpers ----------------------------------------------------
__device__ __forceinline__ uint32_t smem_u32(const void* p) {
    uint32_t a;
    asm("{ .reg .u64 t; cvta.to.shared.u64 t, %1; cvt.u32.u64 %0, t; }"
        : "=r"(a) : "l"(p));
    return a;
}

__device__ __forceinline__ void ldsm4(uint32_t* r, uint32_t addr) {
    asm volatile("ldmatrix.sync.aligned.m8n8.x4.shared.b16 {%0,%1,%2,%3}, [%4];"
        : "=r"(r[0]), "=r"(r[1]), "=r"(r[2]), "=r"(r[3]) : "r"(addr));
}

__device__ __forceinline__ void mma16816(float* d, const uint32_t* a, const uint32_t* b) {
    asm volatile("mma.sync.aligned.m16n8k16.row.col.f32.bf16.bf16.f32 "
        "{%0,%1,%2,%3}, {%4,%5,%6,%7}, {%8,%9}, {%0,%1,%2,%3};"
        : "+f"(d[0]), "+f"(d[1]), "+f"(d[2]), "+f"(d[3])
        : "r"(a[0]), "r"(a[1]), "r"(a[2]), "r"(a[3]), "r"(b[0]), "r"(b[1]));
}

__device__ __forceinline__ uint32_t pk2(float a, float b) {
    union { __nv_bfloat162 v; uint32_t u; } t;
    t.v = __halves2bfloat162(__float2bfloat16_rn(a), __float2bfloat16_rn(b));
    return t.u;
}
__device__ __forceinline__ float bl(uint32_t u, int hi) {
    union { uint32_t u; __nv_bfloat162 v; } t; t.u = u;
    return hi ? __bfloat162float(__high2bfloat16(t.v))
              : __bfloat162float(__low2bfloat16(t.v));
}
__device__ __forceinline__ float silu_f(float a) { return a / (1.0f + expf(-a)); }

// ---------------- small kernels ----------------------------------------------
__global__ void zero_cnt_kernel() { if (threadIdx.x < EE) g_cnt[threadIdx.x] = 0; }

__global__ void gate_kernel(const float* __restrict__ x,
                            const float* __restrict__ Wg) {
    __shared__ float xs[DD];
    __shared__ float part[4][EE];
    int t = blockIdx.x;
    const float* xr = x + (size_t)t * DD;
    for (int i = threadIdx.x; i < DD / 4; i += 128)
        ((float4*)xs)[i] = ((const float4*)xr)[i];
    __syncthreads();
    int e = threadIdx.x & 31, c = threadIdx.x >> 5;
    float s = 0.f;
    for (int d = c * (DD / 4); d < (c + 1) * (DD / 4); d++)
        s += xs[d] * Wg[d * EE + e];
    part[c][e] = s;
    __syncthreads();
    if (threadIdx.x < 32) {
        float logit = part[0][e] + part[1][e] + part[2][e] + part[3][e];
        float m = logit;
        for (int o = 16; o; o >>= 1) m = fmaxf(m, __shfl_xor_sync(~0u, m, o));
        float ex = expf(logit - m);
        float sum = ex;
        for (int o = 16; o; o >>= 1) sum += __shfl_xor_sync(~0u, sum, o);
        float v = ex / sum;
        for (int k = 0; k < KTOP; k++) {
            float bv = v; int bi = e;
            for (int o = 16; o; o >>= 1) {
                float ov = __shfl_xor_sync(~0u, bv, o);
                int   oi = __shfl_xor_sync(~0u, bi, o);
                if (ov > bv || (ov == bv && oi < bi)) { bv = ov; bi = oi; }
            }
            if (e == 0) {
                int slot = atomicAdd(&g_cnt[bi], 1);
                if (slot < CAP) {
                    g_pid[bi * CAP + slot] = t * KTOP + k;
                    g_wt [bi * CAP + slot] = bv;
                }
            }
            if (e == bi) v = -1.0f;
        }
    }
}

// x fp32 -> bf16 hi/lo
__global__ void conv_x_kernel(const float* __restrict__ x) {
    size_t i = (size_t)blockIdx.x * 256 + threadIdx.x;   // float4 index
    float4 v = ((const float4*)x)[i];
    uint32_t h0 = pk2(v.x, v.y), h1 = pk2(v.z, v.w);
    uint32_t l0 = pk2(v.x - bl(h0, 0), v.y - bl(h0, 1));
    uint32_t l1 = pk2(v.z - bl(h1, 0), v.w - bl(h1, 1));
    ((uint2*)g_xhi)[i] = make_uint2(h0, h1);
    ((uint2*)g_xlo)[i] = make_uint2(l0, l1);
}

// transpose + split: src[K][N] fp32 -> dhi/dlo[N][K] bf16; grid (K/32, N/32, z)
__global__ void wt_conv_kernel(const float* __restrict__ src,
                               bf16* __restrict__ dhi, bf16* __restrict__ dlo,
                               int K, int N) {
    size_t zoff = (size_t)blockIdx.z * K * N;
    src += zoff; dhi += zoff; dlo += zoff;
    int k0 = blockIdx.x * 32, n0 = blockIdx.y * 32;
    __shared__ float s[32][33];
    int t = threadIdx.x;
    {
        int kr = t >> 3, c4 = t & 7;
        float4 v = *(const float4*)(src + (size_t)(k0 + kr) * N + n0 + c4 * 4);
        s[kr][c4 * 4 + 0] = v.x; s[kr][c4 * 4 + 1] = v.y;
        s[kr][c4 * 4 + 2] = v.z; s[kr][c4 * 4 + 3] = v.w;
    }
    __syncthreads();
    int nr = t >> 3, k4 = t & 7;
    float f[4] = {s[k4*4+0][nr], s[k4*4+1][nr], s[k4*4+2][nr], s[k4*4+3][nr]};
    uint32_t h0 = pk2(f[0], f[1]), h1 = pk2(f[2], f[3]);
    uint32_t l0 = pk2(f[0] - bl(h0,0), f[1] - bl(h0,1));
    uint32_t l1 = pk2(f[2] - bl(h1,0), f[3] - bl(h1,1));
    size_t off = (size_t)(n0 + nr) * K + k0 + k4 * 4;
    *(uint2*)(dhi + off) = make_uint2(h0, h1);
    *(uint2*)(dlo + off) = make_uint2(l0, l1);
}

// ---------------- mma.sync GEMM kernels --------------------------------------
// smem layouts (SW128 swizzle: 128B rows, cell c xor (row&7)<<4)
#define F1_AH 0
#define F1_AL 16384
#define F1_B1H 32768
#define F1_B1L 40960
#define F1_B3H 49152
#define F1_B3L 57344
#define F1_RW  65536
#define F1_SMEM (65536 + 512)

#define F2_AH 0
#define F2_AL 16384
#define F2_BH 32768
#define F2_BL 40960
#define F2_SMEM 49152

// ffn1: out_hi/lo = split( silu(A@B1) * (A@B3) ); A rows gathered from x split
template<bool SHARED>
__global__ void __launch_bounds__(256)
mm_ffn1(const bf16* __restrict__ b1h_, const bf16* __restrict__ b1l_,
        const bf16* __restrict__ b3h_, const bf16* __restrict__ b3l_,
        bf16* __restrict__ ohi, bf16* __restrict__ olo, int Ntot) {
    extern __shared__ char sm[];
    int e = SHARED ? 0 : blockIdx.z;
    int cnt = SHARED ? TT : min(g_cnt[e], CAP);
    int m0 = blockIdx.y * 128; if (m0 >= cnt) return;
    int n0 = blockIdx.x * 64;
    int tid = threadIdx.x, lane = tid & 31, wid = tid >> 5;
    int wm = (wid >> 1) * 32, wn = (wid & 1) * 32;
    int* rows = (int*)(sm + F1_RW);
    if (tid < 128) {
        int r = m0 + tid;
        rows[tid] = SHARED ? r : ((r < cnt) ? (g_pid[e * CAP + r] >> 2) : 0);
    }
    uint32_t smb = smem_u32(sm);
    size_t boff = (SHARED ? (size_t)0 : (size_t)e * Ntot * DD) + (size_t)n0 * DD;
    const bf16 *B1h = b1h_ + boff, *B1l = b1l_ + boff;
    const bf16 *B3h = b3h_ + boff, *B3l = b3l_ + boff;

    float acc1[2][4][4] = {}, acc3[2][4][4] = {};

    for (int k0 = 0; k0 < DD; k0 += 64) {
        __syncthreads();
#pragma unroll
        for (int i = 0; i < 4; i++) {
            int u = tid + i * 256, r = u >> 3, c = u & 7;
            int off = r * 128 + ((c * 16) ^ ((r & 7) << 4));
            size_t srow = (size_t)rows[r] * DD + k0 + c * 8;
            *(float4*)(sm + F1_AH + off) = *(const float4*)(g_xhi + srow);
            *(float4*)(sm + F1_AL + off) = *(const float4*)(g_xlo + srow);
        }
#pragma unroll
        for (int i = 0; i < 2; i++) {
            int u = tid + i * 256, r = u >> 3, c = u & 7;
            int off = r * 128 + ((c * 16) ^ ((r & 7) << 4));
            size_t srow = (size_t)r * DD + k0 + c * 8;
            *(float4*)(sm + F1_B1H + off) = *(const float4*)(B1h + srow);
            *(float4*)(sm + F1_B1L + off) = *(const float4*)(B1l + srow);
            *(float4*)(sm + F1_B3H + off) = *(const float4*)(B3h + srow);
            *(float4*)(sm + F1_B3L + off) = *(const float4*)(B3l + srow);
        }
        __syncthreads();
#pragma unroll
        for (int ks = 0; ks < 4; ks++) {
            uint32_t ah[2][4], al[2][4];
#pragma unroll
            for (int ma = 0; ma < 2; ma++) {
                int rr = wm + ma * 16 + ((lane >> 3) & 1) * 8 + (lane & 7);
                int kc = ks * 2 + (lane >> 4);
                uint32_t off = rr * 128 + ((kc * 16) ^ ((rr & 7) << 4));
                ldsm4(ah[ma], smb + F1_AH + off);
                ldsm4(al[ma], smb + F1_AL + off);
            }
            int nrb = wn + (lane >> 4) * 8 + (lane & 7);
            int kcb = ks * 2 + ((lane >> 3) & 1);
#pragma unroll
            for (int np = 0; np < 2; np++) {
                int r2 = nrb + np * 16;
                uint32_t off = r2 * 128 + ((kcb * 16) ^ ((r2 & 7) << 4));
                uint32_t bh[4], blo_[4];
                ldsm4(bh,   smb + F1_B1H + off);
                ldsm4(blo_, smb + F1_B1L + off);
#pragma unroll
                for (int s = 0; s < 2; s++) {
                    int na = np * 2 + s;
#pragma unroll
                    for (int ma = 0; ma < 2; ma++) {
                        mma16816(acc1[ma][na], ah[ma], &bh[s * 2]);
                        mma16816(acc1[ma][na], ah[ma], &blo_[s * 2]);
                        mma16816(acc1[ma][na], al[ma], &bh[s * 2]);
                    }
                }
                ldsm4(bh,   smb + F1_B3H + off);
                ldsm4(blo_, smb + F1_B3L + off);
#pragma unroll
                for (int s = 0; s < 2; s++) {
                    int na = np * 2 + s;
#pragma unroll
                    for (int ma = 0; ma < 2; ma++) {
                        mma16816(acc3[ma][na], ah[ma], &bh[s * 2]);
                        mma16816(acc3[ma][na], ah[ma], &blo_[s * 2]);
                        mma16816(acc3[ma][na], al[ma], &bh[s * 2]);
                    }
                }
            }
        }
    }
    // epilogue: silu(acc1)*acc3 -> bf16 hi/lo
#pragma unroll
    for (int ma = 0; ma < 2; ma++)
#pragma unroll
    for (int half = 0; half < 2; half++) {
        int r = m0 + wm + ma * 16 + (lane >> 2) + half * 8;
        if (r >= cnt) continue;
        size_t orow = (SHARED ? (size_t)r : ((size_t)e * CAP + r)) * Ntot;
#pragma unroll
        for (int na = 0; na < 4; na++) {
            float oa = silu_f(acc1[ma][na][half * 2])     * acc3[ma][na][half * 2];
            float ob = silu_f(acc1[ma][na][half * 2 + 1]) * acc3[ma][na][half * 2 + 1];
            uint32_t h = pk2(oa, ob);
            uint32_t l = pk2(oa - bl(h, 0), ob - bl(h, 1));
            int col = n0 + wn + na * 8 + (lane & 3) * 2;
            *(uint32_t*)(ohi + orow + col) = h;
            *(uint32_t*)(olo + orow + col) = l;
        }
    }
}

// ffn2: out = A@B2 (+gate weight for routed); A = hidden hi/lo, contiguous rows
template<bool SHARED>
__global__ void __launch_bounds__(256)
mm_ffn2(const bf16* __restrict__ ahi_, const bf16* __restrict__ alo_,
        const bf16* __restrict__ bhi_, const bf16* __restrict__ blo_,
        float* __restrict__ y, int Kdim) {
    extern __shared__ char sm[];
    int e = SHARED ? 0 : blockIdx.z;
    int cnt = SHARED ? TT : min(g_cnt[e], CAP);
    int m0 = blockIdx.y * 128; if (m0 >= cnt) return;
    int n0 = blockIdx.x * 64;
    int tid = threadIdx.x, lane = tid & 31, wid = tid >> 5;
    int wm = (wid >> 1) * 32, wn = (wid & 1) * 32;
    uint32_t smb = smem_u32(sm);

    size_t arow0 = (SHARED ? (size_t)m0 : ((size_t)e * CAP + m0)) * Kdim;
    const bf16 *Ah = ahi_ + arow0, *Al = alo_ + arow0;
    size_t boff = (SHARED ? (size_t)0 : (size_t)e * DD * Kdim) + (size_t)n0 * Kdim;
    const bf16 *Bh = bhi_ + boff, *Bl = blo_ + boff;

    float acc[2][4][4] = {};

    for (int k0 = 0; k0 < Kdim; k0 += 64) {
        __syncthreads();
#pragma unroll
        for (int i = 0; i < 4; i++) {
            int u = tid + i * 256, r = u >> 3, c = u & 7;
            int off = r * 128 + ((c * 16) ^ ((r & 7) << 4));
            size_t srow = (size_t)r * Kdim + k0 + c * 8;
            *(float4*)(sm + F2_AH + off) = *(const float4*)(Ah + srow);
            *(float4*)(sm + F2_AL + off) = *(const float4*)(Al + srow);
        }
#pragma unroll
        for (int i = 0; i < 2; i++) {
            int u = tid + i * 256, r = u >> 3, c = u & 7;
            int off = r * 128 + ((c * 16) ^ ((r & 7) << 4));
            size_t srow = (size_t)r * Kdim + k0 + c * 8;
            *(float4*)(sm + F2_BH + off) = *(const float4*)(Bh + srow);
            *(float4*)(sm + F2_BL + off) = *(const float4*)(Bl + srow);
        }
        __syncthreads();
#pragma unroll
        for (int ks = 0; ks < 4; ks++) {
            uint32_t ah[2][4], al[2][4];
#pragma unroll
            for (int ma = 0; ma < 2; ma++) {
                int rr = wm + ma * 16 + ((lane >> 3) & 1) * 8 + (lane & 7);
                int kc = ks * 2 + (lane >> 4);
                uint32_t off = rr * 128 + ((kc * 16) ^ ((rr & 7) << 4));
                ldsm4(ah[ma], smb + F2_AH + off);
                ldsm4(al[ma], smb + F2_AL + off);
            }
            int nrb = wn + (lane >> 4) * 8 + (lane & 7);
            int kcb = ks * 2 + ((lane >> 3) & 1);
#pragma unroll
            for (int np = 0; np < 2; np++) {
                int r2 = nrb + np * 16;
                uint32_t off = r2 * 128 + ((kcb * 16) ^ ((r2 & 7) << 4));
                uint32_t bh[4], blo_[4];
                ldsm4(bh,   smb + F2_BH + off);
                ldsm4(blo_, smb + F2_BL + off);
#pragma unroll
                for (int s = 0; s < 2; s++) {
                    int na = np * 2 + s;
#pragma unroll
                    for (int ma = 0; ma < 2; ma++) {
                        mma16816(acc[ma][na], ah[ma], &bh[s * 2]);
                        mma16816(acc[ma][na], ah[ma], &blo_[s * 2]);
                        mma16816(acc[ma][na], al[ma], &bh[s * 2]);
                    }
                }
            }
        }
    }
#pragma unroll
    for (int ma = 0; ma < 2; ma++)
#pragma unroll
    for (int half = 0; half < 2; half++) {
        int r = m0 + wm + ma * 16 + (lane >> 2) + half * 8;
        if (r >= cnt) continue;
        float w = 1.0f;
        float* dst;
        if (SHARED) {
            dst = y + (size_t)r * DD;
        } else {
            int pid = g_pid[e * CAP + r];
            w = g_wt[e * CAP + r];
            dst = g_po + (size_t)pid * DD;
        }
#pragma unroll
        for (int na = 0; na < 4; na++) {
            int col = n0 + wn + na * 8 + (lane & 3) * 2;
            float2 o;
            o.x = acc[ma][na][half * 2]     * w;
            o.y = acc[ma][na][half * 2 + 1] * w;
            *(float2*)(dst + col) = o;
        }
    }
}

// combine: y[t] += sum_k po[t*4+k]
__global__ void combine_kernel(float* __restrict__ y) {
    size_t i  = (size_t)blockIdx.x * 256 + threadIdx.x;
    size_t t  = i >> 8;
    size_t c4 = i & 255;
    float4 acc = ((float4*)y)[i];
    const float4* po4 = (const float4*)g_po;
#pragma unroll
    for (int k = 0; k < KTOP; k++) {
        float4 p = po4[(t * KTOP + k) * (DD / 4) + c4];
        acc.x += p.x; acc.y += p.y; acc.z += p.z; acc.w += p.w;
    }
    ((float4*)y)[i] = acc;
}

// ---------------------------------------------------------------------------
extern "C" void kernel_launch(void* const* d_in, const int* in_sizes, int n_in,
                              void* d_out, int out_size) {
    const float* x   = (const float*)d_in[0];
    const float* Wg  = (const float*)d_in[1];
    const float* W1  = (const float*)d_in[2];
    const float* W2  = (const float*)d_in[3];
    const float* W3  = (const float*)d_in[4];
    const float* Ws1 = (const float*)d_in[5];
    const float* Ws2 = (const float*)d_in[6];
    const float* Ws3 = (const float*)d_in[7];
    float* y = (float*)d_out;

    cudaFuncSetAttribute(mm_ffn1<false>, cudaFuncAttributeMaxDynamicSharedMemorySize, F1_SMEM);
    cudaFuncSetAttribute(mm_ffn1<true >, cudaFuncAttributeMaxDynamicSharedMemorySize, F1_SMEM);
    cudaFuncSetAttribute(mm_ffn2<false>, cudaFuncAttributeMaxDynamicSharedMemorySize, F2_SMEM);
    cudaFuncSetAttribute(mm_ffn2<true >, cudaFuncAttributeMaxDynamicSharedMemorySize, F2_SMEM);

    zero_cnt_kernel<<<1, 32>>>();
    gate_kernel<<<TT, 128>>>(x, Wg);
    conv_x_kernel<<<(TT * DD) / 1024, 256>>>(x);

    wt_conv_kernel<<<dim3(DD/32, HH/32, EE), 256>>>(W1,  g_w1hi,  g_w1lo,  DD, HH);
    wt_conv_kernel<<<dim3(DD/32, HH/32, EE), 256>>>(W3,  g_w3hi,  g_w3lo,  DD, HH);
    wt_conv_kernel<<<dim3(HH/32, DD/32, EE), 256>>>(W2,  g_w2hi,  g_w2lo,  HH, DD);
    wt_conv_kernel<<<dim3(DD/32, HS/32, 1),  256>>>(Ws1, g_ws1hi, g_ws1lo, DD, HS);
    wt_conv_kernel<<<dim3(DD/32, HS/32, 1),  256>>>(Ws3, g_ws3hi, g_ws3lo, DD, HS);
    wt_conv_kernel<<<dim3(HS/32, DD/32, 1),  256>>>(Ws2, g_ws2hi, g_ws2lo, HS, DD);

    mm_ffn1<false><<<dim3(HH/64, CAP/128, EE), 256, F1_SMEM>>>(
        g_w1hi, g_w1lo, g_w3hi, g_w3lo, g_hhi, g_hlo, HH);
    mm_ffn1<true ><<<dim3(HS/64, TT/128, 1), 256, F1_SMEM>>>(
        g_ws1hi, g_ws1lo, g_ws3hi, g_ws3lo, g_hshi, g_hslo, HS);
    mm_ffn2<true ><<<dim3(DD/64, TT/128, 1), 256, F2_SMEM>>>(
        g_hshi, g_hslo, g_ws2hi, g_ws2lo, y, HS);
    mm_ffn2<false><<<dim3(DD/64, CAP/128, EE), 256, F2_SMEM>>>(
        g_hhi, g_hlo, g_w2hi, g_w2lo, y, HH);
    combine_kernel<<<(TT * DD) / 1024, 256>>>(y);
}

// round 16
// speedup vs baseline: 4.1394x; 4.1394x over previous
#include <cuda_runtime.h>
#include <math.h>

#define TT   4096      // tokens
#define DD   1024      // model dim
#define HH   512       // expert hidden
#define EE   32        // experts
#define KTOP 4
#define CAP  2048      // capacity per expert
#define HS   1024      // shared hidden

typedef unsigned long long u64;

// ---------------- scratch (device globals; no allocations allowed) ----------
__device__ int   g_cnt[EE];
__device__ int   g_pid[EE * CAP];              // pair id = tok*4 + k
__device__ float g_wt [EE * CAP];              // gate weight per pair
__device__ float g_h  [(size_t)EE * CAP * HH]; // routed hidden
__device__ float g_hs [(size_t)TT * HS];       // shared hidden
__device__ float g_po [(size_t)TT * KTOP * DD];// per-pair FFN output

// ---------------- f32x2 helpers ---------------------------------------------
__device__ __forceinline__ void fma2(u64& d, u64 a, u64 b) {
    asm("fma.rn.f32x2 %0, %1, %2, %0;" : "+l"(d) : "l"(a), "l"(b));
}
__device__ __forceinline__ u64 dup2(float a) {
    u64 p;
    asm("mov.b64 %0, {%1, %1};" : "=l"(p) : "f"(a));
    return p;
}
__device__ __forceinline__ void unpk(u64 v, float& lo, float& hi) {
    asm("mov.b64 {%0, %1}, %2;" : "=f"(lo), "=f"(hi) : "l"(v));
}
__device__ __forceinline__ float silu_f(float a) { return a / (1.0f + expf(-a)); }

// ---------------- small kernels ----------------------------------------------
__global__ void zero_cnt_kernel() { if (threadIdx.x < EE) g_cnt[threadIdx.x] = 0; }

// one block (128 thr) per token: logits -> softmax -> top4 -> dispatch
__global__ void gate_kernel(const float* __restrict__ x,
                            const float* __restrict__ Wg) {
    __shared__ float xs[DD];
    __shared__ float part[4][EE];
    int t = blockIdx.x;
    const float* xr = x + (size_t)t * DD;
    for (int i = threadIdx.x; i < DD / 4; i += 128)
        ((float4*)xs)[i] = ((const float4*)xr)[i];
    __syncthreads();
    int e = threadIdx.x & 31, c = threadIdx.x >> 5;
    float s = 0.f;
    for (int d = c * (DD / 4); d < (c + 1) * (DD / 4); d++)
        s += xs[d] * Wg[d * EE + e];
    part[c][e] = s;
    __syncthreads();
    if (threadIdx.x < 32) {
        float logit = part[0][e] + part[1][e] + part[2][e] + part[3][e];
        float m = logit;
        for (int o = 16; o; o >>= 1) m = fmaxf(m, __shfl_xor_sync(~0u, m, o));
        float ex = expf(logit - m);
        float sum = ex;
        for (int o = 16; o; o >>= 1) sum += __shfl_xor_sync(~0u, sum, o);
        float v = ex / sum;
        for (int k = 0; k < KTOP; k++) {
            float bv = v; int bi = e;
            for (int o = 16; o; o >>= 1) {
                float ov = __shfl_xor_sync(~0u, bv, o);
                int   oi = __shfl_xor_sync(~0u, bi, o);
                if (ov > bv || (ov == bv && oi < bi)) { bv = ov; bi = oi; }
            }
            if (e == 0) {
                int slot = atomicAdd(&g_cnt[bi], 1);
                if (slot < CAP) {
                    g_pid[bi * CAP + slot] = t * KTOP + k;
                    g_wt [bi * CAP + slot] = bv;
                }
            }
            if (e == bi) v = -1.0f;
        }
    }
}

// ---------------- f32x2 GEMM kernels -----------------------------------------
// Block tile: 64 M x 128 N, BK=16. 256 threads: ty=tid>>4 (4 rows each),
// tx=tid&15 (8 cols: tx*4..+3 and 64+tx*4..+3). Per-thread 4x8 microtile as
// f32x2 pairs. Accumulators: acc[i][jp], jp = {cols tx*4+(0,1)},{(2,3)},
// {64+tx*4+(0,1)},{(2,3)}.

// ffn1: out = silu(A@B1) * (A@B3); A rows gathered (routed) or linear (shared)
template<bool SHARED>
__global__ void __launch_bounds__(256, 2)
ffn1_kernel(const float* __restrict__ x,
            const float* __restrict__ B1, const float* __restrict__ B3,
            float* __restrict__ out, int Ntot) {
    __shared__ float As [16][64];
    __shared__ float B1s[16][128];
    __shared__ float B3s[16][128];
    __shared__ int   rows[64];

    int e  = SHARED ? 0 : blockIdx.z;
    int cnt = SHARED ? TT : min(g_cnt[e], CAP);
    int m0 = blockIdx.y * 64; if (m0 >= cnt) return;
    int n0 = blockIdx.x * 128;
    int tid = threadIdx.x;
    int ty = tid >> 4, tx = tid & 15;

    if (tid < 64) {
        int r = m0 + tid;
        rows[tid] = SHARED ? r : ((r < cnt) ? (g_pid[e * CAP + r] >> 2) : 0);
    }
    __syncthreads();

    size_t boff = (SHARED ? (size_t)0 : (size_t)e * DD * Ntot) + n0;
    const float* B1p = B1 + boff;
    const float* B3p = B3 + boff;

    u64 acc1[4][4] = {}, acc3[4][4] = {};
    int lr = tid >> 2, lk4 = tid & 3;   // A loader coords
    int bk = tid >> 4, bc = (tid & 15) * 4;  // B loader coords

    for (int k0 = 0; k0 < DD; k0 += 16) {
        // load A tile (transposed to [k][m])
        float4 av = *(const float4*)(x + (size_t)rows[lr] * DD + k0 + lk4 * 4);
        As[lk4 * 4 + 0][lr] = av.x; As[lk4 * 4 + 1][lr] = av.y;
        As[lk4 * 4 + 2][lr] = av.z; As[lk4 * 4 + 3][lr] = av.w;
        // load B tiles [k][n] (two 64-col halves)
        const float* b1r = B1p + (size_t)(k0 + bk) * Ntot;
        const float* b3r = B3p + (size_t)(k0 + bk) * Ntot;
        *(float4*)&B1s[bk][bc]      = *(const float4*)(b1r + bc);
        *(float4*)&B1s[bk][64 + bc] = *(const float4*)(b1r + 64 + bc);
        *(float4*)&B3s[bk][bc]      = *(const float4*)(b3r + bc);
        *(float4*)&B3s[bk][64 + bc] = *(const float4*)(b3r + 64 + bc);
        __syncthreads();

#pragma unroll
        for (int kk = 0; kk < 16; kk++) {
            float4 a4 = *(const float4*)&As[kk][ty * 4];
            u64 aa[4] = {dup2(a4.x), dup2(a4.y), dup2(a4.z), dup2(a4.w)};
            ulonglong2 b1a = *(const ulonglong2*)&B1s[kk][tx * 4];
            ulonglong2 b1b = *(const ulonglong2*)&B1s[kk][64 + tx * 4];
            ulonglong2 b3a = *(const ulonglong2*)&B3s[kk][tx * 4];
            ulonglong2 b3b = *(const ulonglong2*)&B3s[kk][64 + tx * 4];
#pragma unroll
            for (int i = 0; i < 4; i++) {
                fma2(acc1[i][0], aa[i], b1a.x);
                fma2(acc1[i][1], aa[i], b1a.y);
                fma2(acc1[i][2], aa[i], b1b.x);
                fma2(acc1[i][3], aa[i], b1b.y);
                fma2(acc3[i][0], aa[i], b3a.x);
                fma2(acc3[i][1], aa[i], b3a.y);
                fma2(acc3[i][2], aa[i], b3b.x);
                fma2(acc3[i][3], aa[i], b3b.y);
            }
        }
        __syncthreads();
    }

#pragma unroll
    for (int i = 0; i < 4; i++) {
        int r = m0 + ty * 4 + i;
        if (r >= cnt) continue;
        size_t orow = (SHARED ? (size_t)r : ((size_t)e * CAP + r)) * Ntot;
        float a0, a1, b0, b1;
        float4 o;
        unpk(acc1[i][0], a0, a1); unpk(acc3[i][0], b0, b1);
        o.x = silu_f(a0) * b0; o.y = silu_f(a1) * b1;
        unpk(acc1[i][1], a0, a1); unpk(acc3[i][1], b0, b1);
        o.z = silu_f(a0) * b0; o.w = silu_f(a1) * b1;
        *(float4*)(out + orow + n0 + tx * 4) = o;
        unpk(acc1[i][2], a0, a1); unpk(acc3[i][2], b0, b1);
        o.x = silu_f(a0) * b0; o.y = silu_f(a1) * b1;
        unpk(acc1[i][3], a0, a1); unpk(acc3[i][3], b0, b1);
        o.z = silu_f(a0) * b0; o.w = silu_f(a1) * b1;
        *(float4*)(out + orow + n0 + 64 + tx * 4) = o;
    }
}

// ffn2: out = A@B; SHARED -> y rows; routed -> g_po[pid] * gate weight
template<bool SHARED>
__global__ void __launch_bounds__(256, 2)
ffn2_kernel(const float* __restrict__ A_, const float* __restrict__ B_,
            float* __restrict__ y, int Kdim) {
    __shared__ float As[16][64];
    __shared__ float Bs[16][128];

    int e  = SHARED ? 0 : blockIdx.z;
    int cnt = SHARED ? TT : min(g_cnt[e], CAP);
    int m0 = blockIdx.y * 64; if (m0 >= cnt) return;
    int n0 = blockIdx.x * 128;
    int tid = threadIdx.x;
    int ty = tid >> 4, tx = tid & 15;

    const float* A = A_ + (SHARED ? (size_t)m0 : ((size_t)e * CAP + m0)) * Kdim;
    const float* B = B_ + (SHARED ? (size_t)0 : (size_t)e * Kdim * DD) + n0;

    u64 acc[4][4] = {};
    int lr = tid >> 2, lk4 = tid & 3;
    int bk = tid >> 4, bc = (tid & 15) * 4;

    for (int k0 = 0; k0 < Kdim; k0 += 16) {
        float4 av = *(const float4*)(A + (size_t)lr * Kdim + k0 + lk4 * 4);
        As[lk4 * 4 + 0][lr] = av.x; As[lk4 * 4 + 1][lr] = av.y;
        As[lk4 * 4 + 2][lr] = av.z; As[lk4 * 4 + 3][lr] = av.w;
        const float* br = B + (size_t)(k0 + bk) * DD;
        *(float4*)&Bs[bk][bc]      = *(const float4*)(br + bc);
        *(float4*)&Bs[bk][64 + bc] = *(const float4*)(br + 64 + bc);
        __syncthreads();

#pragma unroll
        for (int kk = 0; kk < 16; kk++) {
            float4 a4 = *(const float4*)&As[kk][ty * 4];
            u64 aa[4] = {dup2(a4.x), dup2(a4.y), dup2(a4.z), dup2(a4.w)};
            ulonglong2 ba = *(const ulonglong2*)&Bs[kk][tx * 4];
            ulonglong2 bb = *(const ulonglong2*)&Bs[kk][64 + tx * 4];
#pragma unroll
            for (int i = 0; i < 4; i++) {
                fma2(acc[i][0], aa[i], ba.x);
                fma2(acc[i][1], aa[i], ba.y);
                fma2(acc[i][2], aa[i], bb.x);
                fma2(acc[i][3], aa[i], bb.y);
            }
        }
        __syncthreads();
    }

#pragma unroll
    for (int i = 0; i < 4; i++) {
        int r = m0 + ty * 4 + i;
        if (r >= cnt) continue;
        float w = 1.0f;
        float* dst;
        if (SHARED) {
            dst = y + (size_t)r * DD;
        } else {
            int pid = g_pid[e * CAP + r];
            w = g_wt[e * CAP + r];
            dst = g_po + (size_t)pid * DD;
        }
        float v0, v1;
        float4 o;
        unpk(acc[i][0], v0, v1); o.x = v0 * w; o.y = v1 * w;
        unpk(acc[i][1], v0, v1); o.z = v0 * w; o.w = v1 * w;
        *(float4*)(dst + n0 + tx * 4) = o;
        unpk(acc[i][2], v0, v1); o.x = v0 * w; o.y = v1 * w;
        unpk(acc[i][3], v0, v1); o.z = v0 * w; o.w = v1 * w;
        *(float4*)(dst + n0 + 64 + tx * 4) = o;
    }
}

// combine: y[t] += sum_k po[t*4+k]
__global__ void combine_kernel(float* __restrict__ y) {
    size_t i  = (size_t)blockIdx.x * 256 + threadIdx.x;   // float4 index
    size_t t  = i >> 8;
    size_t c4 = i & 255;
    float4 acc = ((float4*)y)[i];
    const float4* po4 = (const float4*)g_po;
#pragma unroll
    for (int k = 0; k < KTOP; k++) {
        float4 p = po4[(t * KTOP + k) * (DD / 4) + c4];
        acc.x += p.x; acc.y += p.y; acc.z += p.z; acc.w += p.w;
    }
    ((float4*)y)[i] = acc;
}

// ---------------------------------------------------------------------------
extern "C" void kernel_launch(void* const* d_in, const int* in_sizes, int n_in,
                              void* d_out, int out_size) {
    const float* x   = (const float*)d_in[0];
    const float* Wg  = (const float*)d_in[1];
    const float* W1  = (const float*)d_in[2];
    const float* W2  = (const float*)d_in[3];
    const float* W3  = (const float*)d_in[4];
    const float* Ws1 = (const float*)d_in[5];
    const float* Ws2 = (const float*)d_in[6];
    const float* Ws3 = (const float*)d_in[7];
    float* y = (float*)d_out;

    zero_cnt_kernel<<<1, 32>>>();
    gate_kernel<<<TT, 128>>>(x, Wg);
    ffn1_kernel<false><<<dim3(HH / 128, CAP / 64, EE), 256>>>(x, W1, W3, g_h, HH);
    ffn1_kernel<true ><<<dim3(HS / 128, TT / 64, 1), 256>>>(x, Ws1, Ws3, g_hs, HS);
    ffn2_kernel<true ><<<dim3(DD / 128, TT / 64, 1), 256>>>(g_hs, Ws2, y, HS);
    ffn2_kernel<false><<<dim3(DD / 128, CAP / 64, EE), 256>>>(g_h, W2, y, HH);
    combine_kernel<<<(TT * DD) / 1024, 256>>>(y);
}